// round 15
// baseline (speedup 1.0000x reference)
#include <cuda_runtime.h>
#include <cuda_bf16.h>
#include <cstdint>

// ---------------------------------------------------------------------------
// Problem constants
// ---------------------------------------------------------------------------
#define BATCH 2
#define SEQ   2048
#define HID   2048
#define VOCAB 32000
#define NSEG  16
#define RANK  256
#define TMATH 1024
#define NMAIN (BATCH*SEQ)   // 4096
#define NROWS 6144          // 4096 main + 2048 math
#define NTILE_N 125         // VOCAB / 256
#define WELEM ((size_t)VOCAB * HID)
#define XELEM ((size_t)NMAIN * HID)

// ---------------------------------------------------------------------------
// Device scratch
// ---------------------------------------------------------------------------
__device__ __nv_bfloat16 g_Wbf[(size_t)VOCAB * HID];     // 131 MB
__device__ __nv_bfloat16 g_Xbf[(size_t)NROWS * HID];     // 25 MB
__device__ float g_inter[(size_t)BATCH * TMATH * RANK];
__device__ float g_pmax[(size_t)NROWS * 256];
__device__ float g_psum[(size_t)NROWS * 256];
__device__ float g_zlab[NROWS];
__device__ float g_nll[NROWS];

// ---------------------------------------------------------------------------
// 1) W + X(main) fp32 -> bf16 in one launch
// ---------------------------------------------------------------------------
__global__ void k_convert_wx(const float* __restrict__ W, const float* __restrict__ h) {
    size_t stride = (size_t)gridDim.x * blockDim.x * 4;
    size_t n = WELEM + XELEM;
    for (size_t j = ((size_t)blockIdx.x * blockDim.x + threadIdx.x) * 4; j < n; j += stride) {
        if (j < WELEM) {
            float4 v = *(const float4*)(W + j);
            *(__nv_bfloat162*)(g_Wbf + j)     = __floats2bfloat162_rn(v.x, v.y);
            *(__nv_bfloat162*)(g_Wbf + j + 2) = __floats2bfloat162_rn(v.z, v.w);
        } else {
            size_t i = j - WELEM;
            float4 v = *(const float4*)(h + i);
            *(__nv_bfloat162*)(g_Xbf + i)     = __floats2bfloat162_rn(v.x, v.y);
            *(__nv_bfloat162*)(g_Xbf + i + 2) = __floats2bfloat162_rn(v.z, v.w);
        }
    }
}

// ---------------------------------------------------------------------------
// 4) adapter stage 1: grid (128 token-groups, 8 r-chunks of 32), 128 thr
// ---------------------------------------------------------------------------
__global__ __launch_bounds__(128) void k_inter(const float* __restrict__ hid,
                                               const float* __restrict__ Bm,
                                               const int* __restrict__ starts) {
    __shared__ float Xs[16][65];
    __shared__ float Bsm[32][65];
    int tgp = blockIdx.x;
    int rc  = blockIdx.y;
    int b   = tgp >> 6;
    int t0  = (tgp & 63) << 4;
    int seg = t0 >> 6;
    int r0  = rc << 5;
    int tid = threadIdx.x;
    int s0  = starts[b];
    int tok = tid & 15, rg = tid >> 4;
    float acc[4];
#pragma unroll
    for (int j = 0; j < 4; j++) acc[j] = 0.f;

    for (int h0 = 0; h0 < HID; h0 += 64) {
#pragma unroll
        for (int i = 0; i < 8; i++) {
            int lin = i * 128 + tid;
            int tk = lin >> 6, hh = lin & 63;
            Xs[tk][hh] = hid[((size_t)(b * SEQ + s0 + t0 + tk)) * HID + h0 + hh];
        }
#pragma unroll
        for (int i = 0; i < 16; i++) {
            int lin = i * 128 + tid;
            int r = lin >> 6, hh = lin & 63;
            Bsm[r][hh] = Bm[((size_t)(seg * RANK + r0 + r)) * HID + h0 + hh];
        }
        __syncthreads();
#pragma unroll 8
        for (int kk = 0; kk < 64; kk++) {
            float xv = Xs[tok][kk];
#pragma unroll
            for (int j = 0; j < 4; j++) acc[j] += xv * Bsm[rg * 4 + j][kk];
        }
        __syncthreads();
    }
#pragma unroll
    for (int j = 0; j < 4; j++)
        g_inter[((size_t)((b << 10) + t0 + tok)) * RANK + r0 + rg * 4 + j] = acc[j];
}

// ---------------------------------------------------------------------------
// 5) adapter stage 2: 21 KB smem, grid (128, 32), 256 thr
// ---------------------------------------------------------------------------
__global__ __launch_bounds__(256) void k_trans(const float* __restrict__ Am,
                                               const float* __restrict__ bias) {
    __shared__ float Is[16][65];
    __shared__ float Asm[64][65];
    int tgp = blockIdx.x;
    int hc  = blockIdx.y;
    int b   = tgp >> 6;
    int t0  = (tgp & 63) << 4;
    int seg = t0 >> 6;
    int h0  = hc << 6;
    int tid = threadIdx.x;
    int tok = tid & 15, hg = tid >> 4;
    float acc[4];
#pragma unroll
    for (int j = 0; j < 4; j++) acc[j] = 0.f;

    for (int r0 = 0; r0 < RANK; r0 += 64) {
#pragma unroll
        for (int i = 0; i < 4; i++) {
            int lin = i * 256 + tid;
            int tk = lin >> 6, rr = lin & 63;
            Is[tk][rr] = g_inter[((size_t)((b << 10) + t0 + tk)) * RANK + r0 + rr];
        }
#pragma unroll
        for (int i = 0; i < 16; i++) {
            int lin = i * 256 + tid;
            int hh = lin >> 6, rr = lin & 63;
            Asm[hh][rr] = Am[((size_t)(seg * HID + h0 + hh)) * RANK + r0 + rr];
        }
        __syncthreads();
#pragma unroll 8
        for (int kk = 0; kk < 64; kk++) {
            float iv = Is[tok][kk];
#pragma unroll
            for (int j = 0; j < 4; j++) acc[j] += iv * Asm[hg * 4 + j][kk];
        }
        __syncthreads();
    }
    size_t row = (size_t)NMAIN + (b << 10) + t0 + tok;
#pragma unroll
    for (int j = 0; j < 4; j++) {
        float v = acc[j] + bias[seg * HID + h0 + hg * 4 + j];
        g_Xbf[row * HID + h0 + hg * 4 + j] = __float2bfloat16(v);
    }
}

// ---------------------------------------------------------------------------
// 6) HMMA GEMM + logsumexp partials
//    CTA 128x256, BK=64, 16 warps (2m x 8n, 64x32 per warp), 512 threads
//    4-stage cp.async ring — identical wait/sync structure to the anchor
// ---------------------------------------------------------------------------
#define STAGES   4
#define KITERS   32
#define SM_A_SZ  16384
#define SM_B_SZ  32768
#define SM_B_OFF (STAGES * SM_A_SZ)
#define SMEM_TOTAL (SM_B_OFF + STAGES * SM_B_SZ)   // 196608

__device__ __forceinline__ void mma16816(float (&c)[4], const uint32_t (&a)[4],
                                         const uint32_t (&b)[2]) {
    asm volatile(
        "mma.sync.aligned.m16n8k16.row.col.f32.bf16.bf16.f32 "
        "{%0,%1,%2,%3}, {%4,%5,%6,%7}, {%8,%9}, {%0,%1,%2,%3};\n"
        : "+f"(c[0]), "+f"(c[1]), "+f"(c[2]), "+f"(c[3])
        : "r"(a[0]), "r"(a[1]), "r"(a[2]), "r"(a[3]), "r"(b[0]), "r"(b[1]));
}

#define LDSM_X4(r0, r1, r2, r3, a) \
    asm volatile("ldmatrix.sync.aligned.m8n8.x4.shared.b16 {%0,%1,%2,%3}, [%4];" \
        : "=r"(r0), "=r"(r1), "=r"(r2), "=r"(r3) : "r"(a))

__device__ __forceinline__ void load_stage(uint32_t sb, int buf, int kk,
                                           const __nv_bfloat16* gA,
                                           const __nv_bfloat16* gB, int tid) {
    const int k0 = kk * 64;
    uint32_t abase = sb + buf * SM_A_SZ;
    uint32_t bbase = sb + SM_B_OFF + buf * SM_B_SZ;
#pragma unroll
    for (int i = 0; i < 6; i++) {
        int lin = i * 512 + tid;
        if (lin < 1024) {
            int row = lin >> 3, c = lin & 7;
            const __nv_bfloat16* src = gA + (size_t)row * HID + k0 + c * 8;
            uint32_t dst = abase + row * 128 + ((c ^ (row & 7)) * 16);
            asm volatile("cp.async.cg.shared.global [%0], [%1], 16;" ::"r"(dst), "l"(src));
        } else {
            int l2 = lin - 1024;
            int row = l2 >> 3, c = l2 & 7;
            const __nv_bfloat16* src = gB + (size_t)row * HID + k0 + c * 8;
            uint32_t dst = bbase + row * 128 + ((c ^ (row & 7)) * 16);
            asm volatile("cp.async.cg.shared.global [%0], [%1], 16;" ::"r"(dst), "l"(src));
        }
    }
    asm volatile("cp.async.commit_group;" ::: "memory");
}

__global__ __launch_bounds__(512, 1) void k_gemm_lse2(int m0,
                                                      const int* __restrict__ starts) {
    const int mTile = m0 + blockIdx.x;
    // dead-tile elimination: main rows s < starts[b]-1 are never consumed
    if (mTile < 32) {
        int b = mTile >> 4, lt = mTile & 15;
        if (lt * 128 + 128 <= starts[b] - 1) return;
    }
    extern __shared__ __align__(1024) char smem[];
    uint32_t sb = (uint32_t)__cvta_generic_to_shared(smem);
    const int tid  = threadIdx.x;
    const int warp = tid >> 5, lane = tid & 31;
    const int wm = warp >> 3, wn = warp & 7;     // 2 x 8 warp grid, 64x32 each
    const int g = lane >> 2, tg = lane & 3;
    const int nTile = blockIdx.y;                // 0..124

    const __nv_bfloat16* gA = g_Xbf + (size_t)mTile * 128 * HID;
    const __nv_bfloat16* gB = g_Wbf + (size_t)nTile * 256 * HID;

    float acc[4][4][4];                           // [mi][ni][frag]
#pragma unroll
    for (int a = 0; a < 4; a++)
#pragma unroll
        for (int q = 0; q < 4; q++)
#pragma unroll
            for (int c = 0; c < 4; c++) acc[a][q][c] = 0.f;

    const int a_row = wm * 64 + (lane & 15);
    const int a_ghi = lane >> 4;
    const int b_row = wn * 32 + (lane & 7) + ((lane >> 4) << 3);
    const int b_ghi = (lane >> 3) & 1;

    load_stage(sb, 0, 0, gA, gB, tid);
    load_stage(sb, 1, 1, gA, gB, tid);
    load_stage(sb, 2, 2, gA, gB, tid);

#pragma unroll 1
    for (int k = 0; k < KITERS; k++) {
        if (k < KITERS - 2)       asm volatile("cp.async.wait_group 2;" ::: "memory");
        else if (k == KITERS - 2) asm volatile("cp.async.wait_group 1;" ::: "memory");
        else                      asm volatile("cp.async.wait_group 0;" ::: "memory");
        __syncthreads();
        if (k + 3 < KITERS) load_stage(sb, (k + 3) % STAGES, k + 3, gA, gB, tid);

        const int buf = k % STAGES;
        const uint32_t abase = sb + buf * SM_A_SZ;
        const uint32_t bbase = sb + SM_B_OFF + buf * SM_B_SZ;
#pragma unroll
        for (int ks = 0; ks < 4; ks++) {
            uint32_t aR[4][4], bR[4][2];
#pragma unroll
            for (int mi = 0; mi < 4; mi++) {
                int r = a_row + mi * 16;
                int gran = ks * 2 + a_ghi;
                uint32_t addr = abase + r * 128 + (((gran ^ (r & 7)) << 4));
                LDSM_X4(aR[mi][0], aR[mi][1], aR[mi][2], aR[mi][3], addr);
            }
#pragma unroll
            for (int np = 0; np < 2; np++) {
                int n = b_row + np * 16;
                int gran = ks * 2 + b_ghi;
                uint32_t addr = bbase + n * 128 + (((gran ^ (n & 7)) << 4));
                LDSM_X4(bR[np * 2][0], bR[np * 2][1], bR[np * 2 + 1][0], bR[np * 2 + 1][1],
                        addr);
            }
#pragma unroll
            for (int mi = 0; mi < 4; mi++)
#pragma unroll
                for (int ni = 0; ni < 4; ni++) mma16816(acc[mi][ni], aR[mi], bR[ni]);
        }
    }

    // ---- epilogue: per-row (max, sum exp) over this 256-col tile ----
    __syncthreads();
    float* red_m = reinterpret_cast<float*>(smem);      // [8 wn][128 rows]
    float* red_s = red_m + 1024;
#pragma unroll
    for (int mi = 0; mi < 4; mi++) {
#pragma unroll
        for (int half = 0; half < 2; half++) {
            float mx = -3.0e38f;
#pragma unroll
            for (int ni = 0; ni < 4; ni++) {
                mx = fmaxf(mx, acc[mi][ni][half * 2 + 0]);
                mx = fmaxf(mx, acc[mi][ni][half * 2 + 1]);
            }
            mx = fmaxf(mx, __shfl_xor_sync(0xffffffffu, mx, 1));
            mx = fmaxf(mx, __shfl_xor_sync(0xffffffffu, mx, 2));
            float s = 0.f;
#pragma unroll
            for (int ni = 0; ni < 4; ni++) {
                s += __expf(acc[mi][ni][half * 2 + 0] - mx);
                s += __expf(acc[mi][ni][half * 2 + 1] - mx);
            }
            s += __shfl_xor_sync(0xffffffffu, s, 1);
            s += __shfl_xor_sync(0xffffffffu, s, 2);
            if (tg == 0) {
                int r = wm * 64 + mi * 16 + half * 8 + g;
                red_m[wn * 128 + r] = mx;
                red_s[wn * 128 + r] = s;
            }
        }
    }
    __syncthreads();
    if (tid < 128) {
        float M = red_m[tid];
#pragma unroll
        for (int j = 1; j < 8; j++) M = fmaxf(M, red_m[j * 128 + tid]);
        float S = 0.f;
#pragma unroll
        for (int j = 0; j < 8; j++)
            S += red_s[j * 128 + tid] * __expf(red_m[j * 128 + tid] - M);
        size_t row = (size_t)mTile * 128 + tid;
        g_pmax[row * 256 + nTile] = M;
        g_psum[row * 256 + nTile] = S;
    }
}

// ---------------------------------------------------------------------------
// 7) label logit per row (label computed inline)
// ---------------------------------------------------------------------------
__global__ __launch_bounds__(256) void k_zlab(const int* __restrict__ ids,
                                              const int* __restrict__ mlab) {
    int row = blockIdx.x, tid = threadIdx.x;
    int lab;
    if (row < NMAIN) {
        int b = row >> 11, s = row & 2047;
        lab = (s < SEQ - 1) ? ids[b * SEQ + s + 1] : 0;
    } else {
        lab = mlab[row - NMAIN];
    }
    const __nv_bfloat16* x = g_Xbf + (size_t)row * HID;
    const __nv_bfloat16* w = g_Wbf + (size_t)lab * HID;
    float s = 0.f;
    for (int i = tid; i < HID; i += 256)
        s += __bfloat162float(x[i]) * __bfloat162float(w[i]);
    __shared__ float red[256];
    red[tid] = s; __syncthreads();
    for (int o = 128; o; o >>= 1) {
        if (tid < o) red[tid] += red[tid + o];
        __syncthreads();
    }
    if (tid == 0) g_zlab[row] = red[0];
}

// ---------------------------------------------------------------------------
// 8) merge (max,sum) partials per row -> nll
// ---------------------------------------------------------------------------
__global__ __launch_bounds__(256) void k_reduce_lse() {
    int row = blockIdx.x, tid = threadIdx.x;
    __shared__ float red[256];
    float m = (tid < NTILE_N) ? g_pmax[(size_t)row * 256 + tid] : -3.0e38f;
    red[tid] = m; __syncthreads();
    for (int o = 128; o; o >>= 1) {
        if (tid < o) red[tid] = fmaxf(red[tid], red[tid + o]);
        __syncthreads();
    }
    float M = red[0]; __syncthreads();
    float s = (tid < NTILE_N) ? g_psum[(size_t)row * 256 + tid] * __expf(m - M) : 0.f;
    red[tid] = s; __syncthreads();
    for (int o = 128; o; o >>= 1) {
        if (tid < o) red[tid] += red[tid + o];
        __syncthreads();
    }
    if (tid == 0) g_nll[row] = M + logf(red[0]) - g_zlab[row];
}

// ---------------------------------------------------------------------------
// 9) masked means + final combination
// ---------------------------------------------------------------------------
__global__ __launch_bounds__(256) void k_final(float* __restrict__ out, int out_size,
                                               const int* __restrict__ starts,
                                               const int* __restrict__ ends,
                                               const int* __restrict__ am,
                                               const int* __restrict__ mam) {
    __shared__ double red[256];
    __shared__ int rl[2];
    __shared__ double totals[6];
    int tid = threadIdx.x;
    for (int i = tid; i < out_size; i += 256) out[i] = 0.f;
    __syncthreads();
    {
        int p0 = 0, p1 = 0;
        for (int s = tid; s < SEQ; s += 256) {
            p0 += am[s];
            p1 += am[SEQ + s];
        }
        red[tid] = (double)p0 + 65536.0 * (double)p1;
        __syncthreads();
        for (int o = 128; o; o >>= 1) {
            if (tid < o) red[tid] += red[tid + o];
            __syncthreads();
        }
        if (tid == 0) {
            long long packed = (long long)(red[0] + 0.5);
            rl[0] = (int)(packed & 0xFFFF);
            rl[1] = (int)(packed >> 16);
        }
        __syncthreads();
    }
    double sums[6] = {0, 0, 0, 0, 0, 0};
    for (int lin = tid; lin < 2 * (SEQ - 1); lin += 256) {
        int b = lin / (SEQ - 1), s = lin - b * (SEQ - 1);
        float v = g_nll[b * SEQ + s];
        int st = starts[b], en = ends[b];
        if (s >= st - 1 && s <= en - 1) { sums[0] += v; sums[1] += 1.0; }
        if (s >= en && s < rl[b] - 1)   { sums[2] += v; sums[3] += 1.0; }
    }
    for (int lin = tid; lin < BATCH * TMATH; lin += 256) {
        double w = (double)mam[lin];
        sums[4] += (double)g_nll[NMAIN + lin] * w;
        sums[5] += w;
    }
    for (int q = 0; q < 6; q++) {
        red[tid] = sums[q]; __syncthreads();
        for (int o = 128; o; o >>= 1) {
            if (tid < o) red[tid] += red[tid + o];
            __syncthreads();
        }
        if (tid == 0) totals[q] = red[0];
        __syncthreads();
    }
    if (tid == 0) {
        double stl = totals[0] / (totals[1] > 1.0 ? totals[1] : 1.0);
        double fal = totals[2] / (totals[3] > 1.0 ? totals[3] : 1.0);
        double ml  = totals[4] / (totals[5] > 1.0 ? totals[5] : 1.0);
        out[0] = (float)(0.5 * ml + 0.5 * stl + 0.4 * fal);
        if (out_size > 1) out[1] = (float)ml;
        if (out_size > 2) out[2] = (float)stl;
        if (out_size > 3) out[3] = (float)fal;
    }
}

// ---------------------------------------------------------------------------
// launch — R8/R11 schedule (trusted anchor):
//   s0: convert_wx -> eW, GEMM main, [eT] GEMM math, [eZ] reduce, final
//   s1: inter, trans -> eT, [eW] zlab -> eZ
// ---------------------------------------------------------------------------
extern "C" void kernel_launch(void* const* d_in, const int* in_sizes, int n_in,
                              void* d_out, int out_size) {
    const float* hid       = (const float*)d_in[0];
    const int*   input_ids = (const int*)  d_in[1];
    const int*   am        = (const int*)  d_in[2];
    const int*   starts    = (const int*)  d_in[3];
    const int*   ends      = (const int*)  d_in[4];
    const int*   mlab      = (const int*)  d_in[5];
    const int*   mam       = (const int*)  d_in[6];
    const float* Am        = (const float*)d_in[8];
    const float* Bm        = (const float*)d_in[9];
    const float* bias      = (const float*)d_in[10];
    const float* W         = (const float*)d_in[11];
    float* out = (float*)d_out;

    cudaFuncSetAttribute(k_gemm_lse2, cudaFuncAttributeMaxDynamicSharedMemorySize,
                         SMEM_TOTAL);

    cudaStream_t s1;
    cudaStreamCreateWithFlags(&s1, cudaStreamNonBlocking);
    cudaEvent_t e0, eW, eT, eZ;
    cudaEventCreateWithFlags(&e0, cudaEventDisableTiming);
    cudaEventCreateWithFlags(&eW, cudaEventDisableTiming);
    cudaEventCreateWithFlags(&eT, cudaEventDisableTiming);
    cudaEventCreateWithFlags(&eZ, cudaEventDisableTiming);

    // fork side stream from the capture stream
    cudaEventRecord(e0, 0);
    cudaStreamWaitEvent(s1, e0, 0);

    // side stream: adapter chain (independent of W conversion)
    k_inter<<<dim3(128, 8), 128, 0, s1>>>(hid, Bm, starts);
    k_trans<<<dim3(128, 32), 256, 0, s1>>>(Am, bias);
    cudaEventRecord(eT, s1);

    // main stream: single conversion launch, then main-row GEMM
    k_convert_wx<<<9216, 256>>>(W, hid);
    cudaEventRecord(eW, 0);
    k_gemm_lse2<<<dim3(32, NTILE_N), 512, SMEM_TOTAL>>>(0, starts);

    // side stream: zlab once W/X(main) ready (math X rows written by trans on s1)
    cudaStreamWaitEvent(s1, eW, 0);
    k_zlab<<<NROWS, 256, 0, s1>>>(input_ids, mlab);
    cudaEventRecord(eZ, s1);

    // main stream: math-row GEMM after trans, then join zlab and reduce
    cudaStreamWaitEvent(0, eT, 0);
    k_gemm_lse2<<<dim3(16, NTILE_N), 512, SMEM_TOTAL>>>(32, starts);
    cudaStreamWaitEvent(0, eZ, 0);
    k_reduce_lse<<<NROWS, 256>>>();
    k_final<<<1, 256>>>(out, out_size, starts, ends, am, mam);
}

// round 16
// speedup vs baseline: 1.0210x; 1.0210x over previous
#include <cuda_runtime.h>
#include <cuda_bf16.h>
#include <cstdint>

// ---------------------------------------------------------------------------
// Problem constants
// ---------------------------------------------------------------------------
#define BATCH 2
#define SEQ   2048
#define HID   2048
#define VOCAB 32000
#define NSEG  16
#define RANK  256
#define TMATH 1024
#define NMAIN (BATCH*SEQ)   // 4096
#define NROWS 6144          // 4096 main + 2048 math
#define NTILE_N 125         // VOCAB / 256
#define WELEM ((size_t)VOCAB * HID)
#define XELEM ((size_t)NMAIN * HID)

// ---------------------------------------------------------------------------
// Device scratch
// ---------------------------------------------------------------------------
__device__ __nv_bfloat16 g_Wbf[(size_t)VOCAB * HID];     // 131 MB
__device__ __nv_bfloat16 g_Xbf[(size_t)NROWS * HID];     // 25 MB
__device__ float g_inter[(size_t)BATCH * TMATH * RANK];
__device__ float g_pmax[(size_t)NROWS * 256];
__device__ float g_psum[(size_t)NROWS * 256];
__device__ float g_zlab[NROWS];
__device__ float g_nll[NROWS];

// ---------------------------------------------------------------------------
// 1) W + X(main) fp32 -> bf16 in one launch
// ---------------------------------------------------------------------------
__global__ void k_convert_wx(const float* __restrict__ W, const float* __restrict__ h) {
    size_t stride = (size_t)gridDim.x * blockDim.x * 4;
    size_t n = WELEM + XELEM;
    for (size_t j = ((size_t)blockIdx.x * blockDim.x + threadIdx.x) * 4; j < n; j += stride) {
        if (j < WELEM) {
            float4 v = *(const float4*)(W + j);
            *(__nv_bfloat162*)(g_Wbf + j)     = __floats2bfloat162_rn(v.x, v.y);
            *(__nv_bfloat162*)(g_Wbf + j + 2) = __floats2bfloat162_rn(v.z, v.w);
        } else {
            size_t i = j - WELEM;
            float4 v = *(const float4*)(h + i);
            *(__nv_bfloat162*)(g_Xbf + i)     = __floats2bfloat162_rn(v.x, v.y);
            *(__nv_bfloat162*)(g_Xbf + i + 2) = __floats2bfloat162_rn(v.z, v.w);
        }
    }
}

// ---------------------------------------------------------------------------
// 4) adapter stage 1: grid (128 token-groups, 8 r-chunks of 32), 128 thr
// ---------------------------------------------------------------------------
__global__ __launch_bounds__(128) void k_inter(const float* __restrict__ hid,
                                               const float* __restrict__ Bm,
                                               const int* __restrict__ starts) {
    __shared__ float Xs[16][65];
    __shared__ float Bsm[32][65];
    int tgp = blockIdx.x;
    int rc  = blockIdx.y;
    int b   = tgp >> 6;
    int t0  = (tgp & 63) << 4;
    int seg = t0 >> 6;
    int r0  = rc << 5;
    int tid = threadIdx.x;
    int s0  = starts[b];
    int tok = tid & 15, rg = tid >> 4;
    float acc[4];
#pragma unroll
    for (int j = 0; j < 4; j++) acc[j] = 0.f;

    for (int h0 = 0; h0 < HID; h0 += 64) {
#pragma unroll
        for (int i = 0; i < 8; i++) {
            int lin = i * 128 + tid;
            int tk = lin >> 6, hh = lin & 63;
            Xs[tk][hh] = hid[((size_t)(b * SEQ + s0 + t0 + tk)) * HID + h0 + hh];
        }
#pragma unroll
        for (int i = 0; i < 16; i++) {
            int lin = i * 128 + tid;
            int r = lin >> 6, hh = lin & 63;
            Bsm[r][hh] = Bm[((size_t)(seg * RANK + r0 + r)) * HID + h0 + hh];
        }
        __syncthreads();
#pragma unroll 8
        for (int kk = 0; kk < 64; kk++) {
            float xv = Xs[tok][kk];
#pragma unroll
            for (int j = 0; j < 4; j++) acc[j] += xv * Bsm[rg * 4 + j][kk];
        }
        __syncthreads();
    }
#pragma unroll
    for (int j = 0; j < 4; j++)
        g_inter[((size_t)((b << 10) + t0 + tok)) * RANK + r0 + rg * 4 + j] = acc[j];
}

// ---------------------------------------------------------------------------
// 5) adapter stage 2: 21 KB smem, grid (128, 32), 256 thr
// ---------------------------------------------------------------------------
__global__ __launch_bounds__(256) void k_trans(const float* __restrict__ Am,
                                               const float* __restrict__ bias) {
    __shared__ float Is[16][65];
    __shared__ float Asm[64][65];
    int tgp = blockIdx.x;
    int hc  = blockIdx.y;
    int b   = tgp >> 6;
    int t0  = (tgp & 63) << 4;
    int seg = t0 >> 6;
    int h0  = hc << 6;
    int tid = threadIdx.x;
    int tok = tid & 15, hg = tid >> 4;
    float acc[4];
#pragma unroll
    for (int j = 0; j < 4; j++) acc[j] = 0.f;

    for (int r0 = 0; r0 < RANK; r0 += 64) {
#pragma unroll
        for (int i = 0; i < 4; i++) {
            int lin = i * 256 + tid;
            int tk = lin >> 6, rr = lin & 63;
            Is[tk][rr] = g_inter[((size_t)((b << 10) + t0 + tk)) * RANK + r0 + rr];
        }
#pragma unroll
        for (int i = 0; i < 16; i++) {
            int lin = i * 256 + tid;
            int hh = lin >> 6, rr = lin & 63;
            Asm[hh][rr] = Am[((size_t)(seg * HID + h0 + hh)) * RANK + r0 + rr];
        }
        __syncthreads();
#pragma unroll 8
        for (int kk = 0; kk < 64; kk++) {
            float iv = Is[tok][kk];
#pragma unroll
            for (int j = 0; j < 4; j++) acc[j] += iv * Asm[hg * 4 + j][kk];
        }
        __syncthreads();
    }
    size_t row = (size_t)NMAIN + (b << 10) + t0 + tok;
#pragma unroll
    for (int j = 0; j < 4; j++) {
        float v = acc[j] + bias[seg * HID + h0 + hg * 4 + j];
        g_Xbf[row * HID + h0 + hg * 4 + j] = __float2bfloat16(v);
    }
}

// ---------------------------------------------------------------------------
// 6) HMMA GEMM + logsumexp partials  (anchor mainloop — DO NOT TOUCH)
//    CTA 128x256, BK=64, 8 warps (2m x 4n), 4-stage cp.async ring
// ---------------------------------------------------------------------------
#define STAGES   4
#define KITERS   32
#define SM_A_SZ  16384
#define SM_B_SZ  32768
#define SM_B_OFF (STAGES * SM_A_SZ)
#define SMEM_TOTAL (SM_B_OFF + STAGES * SM_B_SZ)   // 196608

__device__ __forceinline__ void mma16816(float (&c)[4], const uint32_t (&a)[4],
                                         const uint32_t (&b)[2]) {
    asm volatile(
        "mma.sync.aligned.m16n8k16.row.col.f32.bf16.bf16.f32 "
        "{%0,%1,%2,%3}, {%4,%5,%6,%7}, {%8,%9}, {%0,%1,%2,%3};\n"
        : "+f"(c[0]), "+f"(c[1]), "+f"(c[2]), "+f"(c[3])
        : "r"(a[0]), "r"(a[1]), "r"(a[2]), "r"(a[3]), "r"(b[0]), "r"(b[1]));
}

#define LDSM_X4(r0, r1, r2, r3, a) \
    asm volatile("ldmatrix.sync.aligned.m8n8.x4.shared.b16 {%0,%1,%2,%3}, [%4];" \
        : "=r"(r0), "=r"(r1), "=r"(r2), "=r"(r3) : "r"(a))

__device__ __forceinline__ void load_stage(uint32_t sb, int buf, int kk,
                                           const __nv_bfloat16* gA,
                                           const __nv_bfloat16* gB, int tid) {
    const int k0 = kk * 64;
    uint32_t abase = sb + buf * SM_A_SZ;
    uint32_t bbase = sb + SM_B_OFF + buf * SM_B_SZ;
#pragma unroll
    for (int i = 0; i < 12; i++) {
        int lin = i * 256 + tid;
        if (lin < 1024) {
            int row = lin >> 3, c = lin & 7;
            const __nv_bfloat16* src = gA + (size_t)row * HID + k0 + c * 8;
            uint32_t dst = abase + row * 128 + ((c ^ (row & 7)) * 16);
            asm volatile("cp.async.cg.shared.global [%0], [%1], 16;" ::"r"(dst), "l"(src));
        } else {
            int l2 = lin - 1024;
            int row = l2 >> 3, c = l2 & 7;
            const __nv_bfloat16* src = gB + (size_t)row * HID + k0 + c * 8;
            uint32_t dst = bbase + row * 128 + ((c ^ (row & 7)) * 16);
            asm volatile("cp.async.cg.shared.global [%0], [%1], 16;" ::"r"(dst), "l"(src));
        }
    }
    asm volatile("cp.async.commit_group;" ::: "memory");
}

__global__ __launch_bounds__(256, 1) void k_gemm_lse2(int m0,
                                                      const int* __restrict__ starts) {
    const int mTile = m0 + blockIdx.x;
    // dead-tile elimination: main rows s < starts[b]-1 are never consumed
    if (mTile < 32) {
        int b = mTile >> 4, lt = mTile & 15;
        if (lt * 128 + 128 <= starts[b] - 1) return;
    }
    extern __shared__ __align__(1024) char smem[];
    uint32_t sb = (uint32_t)__cvta_generic_to_shared(smem);
    const int tid  = threadIdx.x;
    const int warp = tid >> 5, lane = tid & 31;
    const int wm = warp >> 2, wn = warp & 3;
    const int g = lane >> 2, tg = lane & 3;
    const int nTile = blockIdx.y;                // 0..124

    const __nv_bfloat16* gA = g_Xbf + (size_t)mTile * 128 * HID;
    const __nv_bfloat16* gB = g_Wbf + (size_t)nTile * 256 * HID;

    float acc[4][8][4];
#pragma unroll
    for (int a = 0; a < 4; a++)
#pragma unroll
        for (int q = 0; q < 8; q++)
#pragma unroll
            for (int c = 0; c < 4; c++) acc[a][q][c] = 0.f;

    const int a_row = wm * 64 + (lane & 15);
    const int a_ghi = lane >> 4;
    const int b_row = wn * 64 + (lane & 7) + ((lane >> 4) << 3);
    const int b_ghi = (lane >> 3) & 1;

    load_stage(sb, 0, 0, gA, gB, tid);
    load_stage(sb, 1, 1, gA, gB, tid);
    load_stage(sb, 2, 2, gA, gB, tid);

#pragma unroll 1
    for (int k = 0; k < KITERS; k++) {
        if (k < KITERS - 2)       asm volatile("cp.async.wait_group 2;" ::: "memory");
        else if (k == KITERS - 2) asm volatile("cp.async.wait_group 1;" ::: "memory");
        else                      asm volatile("cp.async.wait_group 0;" ::: "memory");
        __syncthreads();
        if (k + 3 < KITERS) load_stage(sb, (k + 3) % STAGES, k + 3, gA, gB, tid);

        const int buf = k % STAGES;
        const uint32_t abase = sb + buf * SM_A_SZ;
        const uint32_t bbase = sb + SM_B_OFF + buf * SM_B_SZ;
#pragma unroll
        for (int ks = 0; ks < 4; ks++) {
            uint32_t aR[4][4], bR[8][2];
#pragma unroll
            for (int mi = 0; mi < 4; mi++) {
                int r = a_row + mi * 16;
                int gran = ks * 2 + a_ghi;
                uint32_t addr = abase + r * 128 + (((gran ^ (r & 7)) << 4));
                LDSM_X4(aR[mi][0], aR[mi][1], aR[mi][2], aR[mi][3], addr);
            }
#pragma unroll
            for (int np = 0; np < 4; np++) {
                int n = b_row + np * 16;
                int gran = ks * 2 + b_ghi;
                uint32_t addr = bbase + n * 128 + (((gran ^ (n & 7)) << 4));
                LDSM_X4(bR[np * 2][0], bR[np * 2][1], bR[np * 2 + 1][0], bR[np * 2 + 1][1],
                        addr);
            }
#pragma unroll
            for (int mi = 0; mi < 4; mi++)
#pragma unroll
                for (int ni = 0; ni < 8; ni++) mma16816(acc[mi][ni], aR[mi], bR[ni]);
        }
    }

    // ---- epilogue: per-row (max, sum exp) over this 256-col tile ----
    __syncthreads();
    float* red_m = reinterpret_cast<float*>(smem);
    float* red_s = red_m + 512;
#pragma unroll
    for (int mi = 0; mi < 4; mi++) {
#pragma unroll
        for (int half = 0; half < 2; half++) {
            float mx = -3.0e38f;
#pragma unroll
            for (int ni = 0; ni < 8; ni++) {
                mx = fmaxf(mx, acc[mi][ni][half * 2 + 0]);
                mx = fmaxf(mx, acc[mi][ni][half * 2 + 1]);
            }
            mx = fmaxf(mx, __shfl_xor_sync(0xffffffffu, mx, 1));
            mx = fmaxf(mx, __shfl_xor_sync(0xffffffffu, mx, 2));
            float s = 0.f;
#pragma unroll
            for (int ni = 0; ni < 8; ni++) {
                s += __expf(acc[mi][ni][half * 2 + 0] - mx);
                s += __expf(acc[mi][ni][half * 2 + 1] - mx);
            }
            s += __shfl_xor_sync(0xffffffffu, s, 1);
            s += __shfl_xor_sync(0xffffffffu, s, 2);
            if (tg == 0) {
                int r = wm * 64 + mi * 16 + half * 8 + g;
                red_m[wn * 128 + r] = mx;
                red_s[wn * 128 + r] = s;
            }
        }
    }
    __syncthreads();
    if (tid < 128) {
        float M = red_m[tid];
#pragma unroll
        for (int j = 1; j < 4; j++) M = fmaxf(M, red_m[j * 128 + tid]);
        float S = 0.f;
#pragma unroll
        for (int j = 0; j < 4; j++)
            S += red_s[j * 128 + tid] * __expf(red_m[j * 128 + tid] - M);
        size_t row = (size_t)mTile * 128 + tid;
        g_pmax[row * 256 + nTile] = M;
        g_psum[row * 256 + nTile] = S;
    }
}

// ---------------------------------------------------------------------------
// 7) label logit per row (label computed inline)
// ---------------------------------------------------------------------------
__global__ __launch_bounds__(256) void k_zlab(const int* __restrict__ ids,
                                              const int* __restrict__ mlab) {
    int row = blockIdx.x, tid = threadIdx.x;
    int lab;
    if (row < NMAIN) {
        int b = row >> 11, s = row & 2047;
        lab = (s < SEQ - 1) ? ids[b * SEQ + s + 1] : 0;
    } else {
        lab = mlab[row - NMAIN];
    }
    const __nv_bfloat16* x = g_Xbf + (size_t)row * HID;
    const __nv_bfloat16* w = g_Wbf + (size_t)lab * HID;
    float s = 0.f;
    for (int i = tid; i < HID; i += 256)
        s += __bfloat162float(x[i]) * __bfloat162float(w[i]);
    __shared__ float red[256];
    red[tid] = s; __syncthreads();
    for (int o = 128; o; o >>= 1) {
        if (tid < o) red[tid] += red[tid + o];
        __syncthreads();
    }
    if (tid == 0) g_zlab[row] = red[0];
}

// ---------------------------------------------------------------------------
// 8) merge (max,sum) partials per row -> nll
// ---------------------------------------------------------------------------
__global__ __launch_bounds__(256) void k_reduce_lse() {
    int row = blockIdx.x, tid = threadIdx.x;
    __shared__ float red[256];
    float m = (tid < NTILE_N) ? g_pmax[(size_t)row * 256 + tid] : -3.0e38f;
    red[tid] = m; __syncthreads();
    for (int o = 128; o; o >>= 1) {
        if (tid < o) red[tid] = fmaxf(red[tid], red[tid + o]);
        __syncthreads();
    }
    float M = red[0]; __syncthreads();
    float s = (tid < NTILE_N) ? g_psum[(size_t)row * 256 + tid] * __expf(m - M) : 0.f;
    red[tid] = s; __syncthreads();
    for (int o = 128; o; o >>= 1) {
        if (tid < o) red[tid] += red[tid + o];
        __syncthreads();
    }
    if (tid == 0) g_nll[row] = M + logf(red[0]) - g_zlab[row];
}

// ---------------------------------------------------------------------------
// 9) masked means + final combination
// ---------------------------------------------------------------------------
__global__ __launch_bounds__(256) void k_final(float* __restrict__ out, int out_size,
                                               const int* __restrict__ starts,
                                               const int* __restrict__ ends,
                                               const int* __restrict__ am,
                                               const int* __restrict__ mam) {
    __shared__ double red[256];
    __shared__ int rl[2];
    __shared__ double totals[6];
    int tid = threadIdx.x;
    for (int i = tid; i < out_size; i += 256) out[i] = 0.f;
    __syncthreads();
    {
        int p0 = 0, p1 = 0;
        for (int s = tid; s < SEQ; s += 256) {
            p0 += am[s];
            p1 += am[SEQ + s];
        }
        red[tid] = (double)p0 + 65536.0 * (double)p1;
        __syncthreads();
        for (int o = 128; o; o >>= 1) {
            if (tid < o) red[tid] += red[tid + o];
            __syncthreads();
        }
        if (tid == 0) {
            long long packed = (long long)(red[0] + 0.5);
            rl[0] = (int)(packed & 0xFFFF);
            rl[1] = (int)(packed >> 16);
        }
        __syncthreads();
    }
    double sums[6] = {0, 0, 0, 0, 0, 0};
    for (int lin = tid; lin < 2 * (SEQ - 1); lin += 256) {
        int b = lin / (SEQ - 1), s = lin - b * (SEQ - 1);
        float v = g_nll[b * SEQ + s];
        int st = starts[b], en = ends[b];
        if (s >= st - 1 && s <= en - 1) { sums[0] += v; sums[1] += 1.0; }
        if (s >= en && s < rl[b] - 1)   { sums[2] += v; sums[3] += 1.0; }
    }
    for (int lin = tid; lin < BATCH * TMATH; lin += 256) {
        double w = (double)mam[lin];
        sums[4] += (double)g_nll[NMAIN + lin] * w;
        sums[5] += w;
    }
    for (int q = 0; q < 6; q++) {
        red[tid] = sums[q]; __syncthreads();
        for (int o = 128; o; o >>= 1) {
            if (tid < o) red[tid] += red[tid + o];
            __syncthreads();
        }
        if (tid == 0) totals[q] = red[0];
        __syncthreads();
    }
    if (tid == 0) {
        double stl = totals[0] / (totals[1] > 1.0 ? totals[1] : 1.0);
        double fal = totals[2] / (totals[3] > 1.0 ? totals[3] : 1.0);
        double ml  = totals[4] / (totals[5] > 1.0 ? totals[5] : 1.0);
        out[0] = (float)(0.5 * ml + 0.5 * stl + 0.4 * fal);
        if (out_size > 1) out[1] = (float)ml;
        if (out_size > 2) out[2] = (float)stl;
        if (out_size > 3) out[3] = (float)fal;
    }
}

// ---------------------------------------------------------------------------
// launch — anchor schedule + math-GEMM tail overlap:
//   s0: convert_wx -> eW, GEMM main, [eG] reduce, final
//   s1: inter, trans, [eW] zlab, GEMM math -> eG
//   (math GEMM on s1 fills SMs as the main GEMM's ragged tail retires)
// ---------------------------------------------------------------------------
extern "C" void kernel_launch(void* const* d_in, const int* in_sizes, int n_in,
                              void* d_out, int out_size) {
    const float* hid       = (const float*)d_in[0];
    const int*   input_ids = (const int*)  d_in[1];
    const int*   am        = (const int*)  d_in[2];
    const int*   starts    = (const int*)  d_in[3];
    const int*   ends      = (const int*)  d_in[4];
    const int*   mlab      = (const int*)  d_in[5];
    const int*   mam       = (const int*)  d_in[6];
    const float* Am        = (const float*)d_in[8];
    const float* Bm        = (const float*)d_in[9];
    const float* bias      = (const float*)d_in[10];
    const float* W         = (const float*)d_in[11];
    float* out = (float*)d_out;

    cudaFuncSetAttribute(k_gemm_lse2, cudaFuncAttributeMaxDynamicSharedMemorySize,
                         SMEM_TOTAL);

    cudaStream_t s1;
    cudaStreamCreateWithFlags(&s1, cudaStreamNonBlocking);
    cudaEvent_t e0, eW, eG;
    cudaEventCreateWithFlags(&e0, cudaEventDisableTiming);
    cudaEventCreateWithFlags(&eW, cudaEventDisableTiming);
    cudaEventCreateWithFlags(&eG, cudaEventDisableTiming);

    // fork side stream from the capture stream
    cudaEventRecord(e0, 0);
    cudaStreamWaitEvent(s1, e0, 0);

    // side stream: adapter chain (independent of W conversion)
    k_inter<<<dim3(128, 8), 128, 0, s1>>>(hid, Bm, starts);
    k_trans<<<dim3(128, 32), 256, 0, s1>>>(Am, bias);

    // main stream: single conversion launch, then main-row GEMM
    k_convert_wx<<<9216, 256>>>(W, hid);
    cudaEventRecord(eW, 0);
    k_gemm_lse2<<<dim3(32, NTILE_N), 256, SMEM_TOTAL>>>(0, starts);

    // side stream: zlab then math-row GEMM (needs eW for W; trans by s1 order).
    // The math GEMM overlaps the main GEMM's tail on s0.
    cudaStreamWaitEvent(s1, eW, 0);
    k_zlab<<<NROWS, 256, 0, s1>>>(input_ids, mlab);
    k_gemm_lse2<<<dim3(16, NTILE_N), 256, SMEM_TOTAL, s1>>>(32, starts);
    cudaEventRecord(eG, s1);

    // main stream: join everything, then reduce + final
    cudaStreamWaitEvent(0, eG, 0);
    k_reduce_lse<<<NROWS, 256>>>();
    k_final<<<1, 256>>>(out, out_size, starts, ends, am, mam);
}

// round 17
// speedup vs baseline: 1.0250x; 1.0040x over previous
#include <cuda_runtime.h>
#include <cuda_bf16.h>
#include <cstdint>

// ---------------------------------------------------------------------------
// Problem constants
// ---------------------------------------------------------------------------
#define BATCH 2
#define SEQ   2048
#define HID   2048
#define VOCAB 32000
#define NSEG  16
#define RANK  256
#define TMATH 1024
#define NMAIN (BATCH*SEQ)   // 4096
#define NROWS 6144          // 4096 main + 2048 math
#define NTILE_N 125         // VOCAB / 256
#define WELEM ((size_t)VOCAB * HID)
#define XELEM ((size_t)NMAIN * HID)

// ---------------------------------------------------------------------------
// Device scratch
// ---------------------------------------------------------------------------
__device__ __nv_bfloat16 g_Wbf[(size_t)VOCAB * HID];     // 131 MB
__device__ __nv_bfloat16 g_Xbf[(size_t)NROWS * HID];     // 25 MB
__device__ float g_inter[(size_t)BATCH * TMATH * RANK];
__device__ float g_pmax[(size_t)NROWS * 256];
__device__ float g_psum[(size_t)NROWS * 256];
__device__ float g_zlab[NROWS];
__device__ float g_nll[NROWS];

// ---------------------------------------------------------------------------
// 1) W + X(main) fp32 -> bf16 in one launch
// ---------------------------------------------------------------------------
__global__ void k_convert_wx(const float* __restrict__ W, const float* __restrict__ h) {
    size_t stride = (size_t)gridDim.x * blockDim.x * 4;
    size_t n = WELEM + XELEM;
    for (size_t j = ((size_t)blockIdx.x * blockDim.x + threadIdx.x) * 4; j < n; j += stride) {
        if (j < WELEM) {
            float4 v = *(const float4*)(W + j);
            *(__nv_bfloat162*)(g_Wbf + j)     = __floats2bfloat162_rn(v.x, v.y);
            *(__nv_bfloat162*)(g_Wbf + j + 2) = __floats2bfloat162_rn(v.z, v.w);
        } else {
            size_t i = j - WELEM;
            float4 v = *(const float4*)(h + i);
            *(__nv_bfloat162*)(g_Xbf + i)     = __floats2bfloat162_rn(v.x, v.y);
            *(__nv_bfloat162*)(g_Xbf + i + 2) = __floats2bfloat162_rn(v.z, v.w);
        }
    }
}

// ---------------------------------------------------------------------------
// 4) adapter stage 1: grid (128 token-groups, 8 r-chunks of 32), 128 thr
// ---------------------------------------------------------------------------
__global__ __launch_bounds__(128) void k_inter(const float* __restrict__ hid,
                                               const float* __restrict__ Bm,
                                               const int* __restrict__ starts) {
    __shared__ float Xs[16][65];
    __shared__ float Bsm[32][65];
    int tgp = blockIdx.x;
    int rc  = blockIdx.y;
    int b   = tgp >> 6;
    int t0  = (tgp & 63) << 4;
    int seg = t0 >> 6;
    int r0  = rc << 5;
    int tid = threadIdx.x;
    int s0  = starts[b];
    int tok = tid & 15, rg = tid >> 4;
    float acc[4];
#pragma unroll
    for (int j = 0; j < 4; j++) acc[j] = 0.f;

    for (int h0 = 0; h0 < HID; h0 += 64) {
#pragma unroll
        for (int i = 0; i < 8; i++) {
            int lin = i * 128 + tid;
            int tk = lin >> 6, hh = lin & 63;
            Xs[tk][hh] = hid[((size_t)(b * SEQ + s0 + t0 + tk)) * HID + h0 + hh];
        }
#pragma unroll
        for (int i = 0; i < 16; i++) {
            int lin = i * 128 + tid;
            int r = lin >> 6, hh = lin & 63;
            Bsm[r][hh] = Bm[((size_t)(seg * RANK + r0 + r)) * HID + h0 + hh];
        }
        __syncthreads();
#pragma unroll 8
        for (int kk = 0; kk < 64; kk++) {
            float xv = Xs[tok][kk];
#pragma unroll
            for (int j = 0; j < 4; j++) acc[j] += xv * Bsm[rg * 4 + j][kk];
        }
        __syncthreads();
    }
#pragma unroll
    for (int j = 0; j < 4; j++)
        g_inter[((size_t)((b << 10) + t0 + tok)) * RANK + r0 + rg * 4 + j] = acc[j];
}

// ---------------------------------------------------------------------------
// 5) adapter stage 2: 21 KB smem, grid (128, 32), 256 thr
// ---------------------------------------------------------------------------
__global__ __launch_bounds__(256) void k_trans(const float* __restrict__ Am,
                                               const float* __restrict__ bias) {
    __shared__ float Is[16][65];
    __shared__ float Asm[64][65];
    int tgp = blockIdx.x;
    int hc  = blockIdx.y;
    int b   = tgp >> 6;
    int t0  = (tgp & 63) << 4;
    int seg = t0 >> 6;
    int h0  = hc << 6;
    int tid = threadIdx.x;
    int tok = tid & 15, hg = tid >> 4;
    float acc[4];
#pragma unroll
    for (int j = 0; j < 4; j++) acc[j] = 0.f;

    for (int r0 = 0; r0 < RANK; r0 += 64) {
#pragma unroll
        for (int i = 0; i < 4; i++) {
            int lin = i * 256 + tid;
            int tk = lin >> 6, rr = lin & 63;
            Is[tk][rr] = g_inter[((size_t)((b << 10) + t0 + tk)) * RANK + r0 + rr];
        }
#pragma unroll
        for (int i = 0; i < 16; i++) {
            int lin = i * 256 + tid;
            int hh = lin >> 6, rr = lin & 63;
            Asm[hh][rr] = Am[((size_t)(seg * HID + h0 + hh)) * RANK + r0 + rr];
        }
        __syncthreads();
#pragma unroll 8
        for (int kk = 0; kk < 64; kk++) {
            float iv = Is[tok][kk];
#pragma unroll
            for (int j = 0; j < 4; j++) acc[j] += iv * Asm[hg * 4 + j][kk];
        }
        __syncthreads();
    }
    size_t row = (size_t)NMAIN + (b << 10) + t0 + tok;
#pragma unroll
    for (int j = 0; j < 4; j++) {
        float v = acc[j] + bias[seg * HID + h0 + hg * 4 + j];
        g_Xbf[row * HID + h0 + hg * 4 + j] = __float2bfloat16(v);
    }
}

// ---------------------------------------------------------------------------
// 6) HMMA GEMM + logsumexp partials  (anchor mainloop — DO NOT TOUCH)
//    CTA 128x256, BK=64, 8 warps (2m x 4n), 4-stage cp.async ring
// ---------------------------------------------------------------------------
#define STAGES   4
#define KITERS   32
#define SM_A_SZ  16384
#define SM_B_SZ  32768
#define SM_B_OFF (STAGES * SM_A_SZ)
#define SMEM_TOTAL (SM_B_OFF + STAGES * SM_B_SZ)   // 196608

__device__ __forceinline__ void mma16816(float (&c)[4], const uint32_t (&a)[4],
                                         const uint32_t (&b)[2]) {
    asm volatile(
        "mma.sync.aligned.m16n8k16.row.col.f32.bf16.bf16.f32 "
        "{%0,%1,%2,%3}, {%4,%5,%6,%7}, {%8,%9}, {%0,%1,%2,%3};\n"
        : "+f"(c[0]), "+f"(c[1]), "+f"(c[2]), "+f"(c[3])
        : "r"(a[0]), "r"(a[1]), "r"(a[2]), "r"(a[3]), "r"(b[0]), "r"(b[1]));
}

#define LDSM_X4(r0, r1, r2, r3, a) \
    asm volatile("ldmatrix.sync.aligned.m8n8.x4.shared.b16 {%0,%1,%2,%3}, [%4];" \
        : "=r"(r0), "=r"(r1), "=r"(r2), "=r"(r3) : "r"(a))

__device__ __forceinline__ void load_stage(uint32_t sb, int buf, int kk,
                                           const __nv_bfloat16* gA,
                                           const __nv_bfloat16* gB, int tid) {
    const int k0 = kk * 64;
    uint32_t abase = sb + buf * SM_A_SZ;
    uint32_t bbase = sb + SM_B_OFF + buf * SM_B_SZ;
#pragma unroll
    for (int i = 0; i < 12; i++) {
        int lin = i * 256 + tid;
        if (lin < 1024) {
            int row = lin >> 3, c = lin & 7;
            const __nv_bfloat16* src = gA + (size_t)row * HID + k0 + c * 8;
            uint32_t dst = abase + row * 128 + ((c ^ (row & 7)) * 16);
            asm volatile("cp.async.cg.shared.global [%0], [%1], 16;" ::"r"(dst), "l"(src));
        } else {
            int l2 = lin - 1024;
            int row = l2 >> 3, c = l2 & 7;
            const __nv_bfloat16* src = gB + (size_t)row * HID + k0 + c * 8;
            uint32_t dst = bbase + row * 128 + ((c ^ (row & 7)) * 16);
            asm volatile("cp.async.cg.shared.global [%0], [%1], 16;" ::"r"(dst), "l"(src));
        }
    }
    asm volatile("cp.async.commit_group;" ::: "memory");
}

__global__ __launch_bounds__(256, 1) void k_gemm_lse2(int m0,
                                                      const int* __restrict__ starts) {
    const int mTile = m0 + blockIdx.x;
    // dead-tile elimination: main rows s < starts[b]-1 are never consumed
    if (mTile < 32) {
        int b = mTile >> 4, lt = mTile & 15;
        if (lt * 128 + 128 <= starts[b] - 1) return;
    }
    extern __shared__ __align__(1024) char smem[];
    uint32_t sb = (uint32_t)__cvta_generic_to_shared(smem);
    const int tid  = threadIdx.x;
    const int warp = tid >> 5, lane = tid & 31;
    const int wm = warp >> 2, wn = warp & 3;
    const int g = lane >> 2, tg = lane & 3;
    const int nTile = blockIdx.y;                // 0..124

    const __nv_bfloat16* gA = g_Xbf + (size_t)mTile * 128 * HID;
    const __nv_bfloat16* gB = g_Wbf + (size_t)nTile * 256 * HID;

    float acc[4][8][4];
#pragma unroll
    for (int a = 0; a < 4; a++)
#pragma unroll
        for (int q = 0; q < 8; q++)
#pragma unroll
            for (int c = 0; c < 4; c++) acc[a][q][c] = 0.f;

    const int a_row = wm * 64 + (lane & 15);
    const int a_ghi = lane >> 4;
    const int b_row = wn * 64 + (lane & 7) + ((lane >> 4) << 3);
    const int b_ghi = (lane >> 3) & 1;

    load_stage(sb, 0, 0, gA, gB, tid);
    load_stage(sb, 1, 1, gA, gB, tid);
    load_stage(sb, 2, 2, gA, gB, tid);

#pragma unroll 1
    for (int k = 0; k < KITERS; k++) {
        if (k < KITERS - 2)       asm volatile("cp.async.wait_group 2;" ::: "memory");
        else if (k == KITERS - 2) asm volatile("cp.async.wait_group 1;" ::: "memory");
        else                      asm volatile("cp.async.wait_group 0;" ::: "memory");
        __syncthreads();
        if (k + 3 < KITERS) load_stage(sb, (k + 3) % STAGES, k + 3, gA, gB, tid);

        const int buf = k % STAGES;
        const uint32_t abase = sb + buf * SM_A_SZ;
        const uint32_t bbase = sb + SM_B_OFF + buf * SM_B_SZ;
#pragma unroll
        for (int ks = 0; ks < 4; ks++) {
            uint32_t aR[4][4], bR[8][2];
#pragma unroll
            for (int mi = 0; mi < 4; mi++) {
                int r = a_row + mi * 16;
                int gran = ks * 2 + a_ghi;
                uint32_t addr = abase + r * 128 + (((gran ^ (r & 7)) << 4));
                LDSM_X4(aR[mi][0], aR[mi][1], aR[mi][2], aR[mi][3], addr);
            }
#pragma unroll
            for (int np = 0; np < 4; np++) {
                int n = b_row + np * 16;
                int gran = ks * 2 + b_ghi;
                uint32_t addr = bbase + n * 128 + (((gran ^ (n & 7)) << 4));
                LDSM_X4(bR[np * 2][0], bR[np * 2][1], bR[np * 2 + 1][0], bR[np * 2 + 1][1],
                        addr);
            }
#pragma unroll
            for (int mi = 0; mi < 4; mi++)
#pragma unroll
                for (int ni = 0; ni < 8; ni++) mma16816(acc[mi][ni], aR[mi], bR[ni]);
        }
    }

    // ---- epilogue: per-row (max, sum exp) over this 256-col tile ----
    __syncthreads();
    float* red_m = reinterpret_cast<float*>(smem);
    float* red_s = red_m + 512;
#pragma unroll
    for (int mi = 0; mi < 4; mi++) {
#pragma unroll
        for (int half = 0; half < 2; half++) {
            float mx = -3.0e38f;
#pragma unroll
            for (int ni = 0; ni < 8; ni++) {
                mx = fmaxf(mx, acc[mi][ni][half * 2 + 0]);
                mx = fmaxf(mx, acc[mi][ni][half * 2 + 1]);
            }
            mx = fmaxf(mx, __shfl_xor_sync(0xffffffffu, mx, 1));
            mx = fmaxf(mx, __shfl_xor_sync(0xffffffffu, mx, 2));
            float s = 0.f;
#pragma unroll
            for (int ni = 0; ni < 8; ni++) {
                s += __expf(acc[mi][ni][half * 2 + 0] - mx);
                s += __expf(acc[mi][ni][half * 2 + 1] - mx);
            }
            s += __shfl_xor_sync(0xffffffffu, s, 1);
            s += __shfl_xor_sync(0xffffffffu, s, 2);
            if (tg == 0) {
                int r = wm * 64 + mi * 16 + half * 8 + g;
                red_m[wn * 128 + r] = mx;
                red_s[wn * 128 + r] = s;
            }
        }
    }
    __syncthreads();
    if (tid < 128) {
        float M = red_m[tid];
#pragma unroll
        for (int j = 1; j < 4; j++) M = fmaxf(M, red_m[j * 128 + tid]);
        float S = 0.f;
#pragma unroll
        for (int j = 0; j < 4; j++)
            S += red_s[j * 128 + tid] * __expf(red_m[j * 128 + tid] - M);
        size_t row = (size_t)mTile * 128 + tid;
        g_pmax[row * 256 + nTile] = M;
        g_psum[row * 256 + nTile] = S;
    }
}

// ---------------------------------------------------------------------------
// 7) label logit per row (label computed inline)
// ---------------------------------------------------------------------------
__global__ __launch_bounds__(256) void k_zlab(const int* __restrict__ ids,
                                              const int* __restrict__ mlab) {
    int row = blockIdx.x, tid = threadIdx.x;
    int lab;
    if (row < NMAIN) {
        int b = row >> 11, s = row & 2047;
        lab = (s < SEQ - 1) ? ids[b * SEQ + s + 1] : 0;
    } else {
        lab = mlab[row - NMAIN];
    }
    const __nv_bfloat16* x = g_Xbf + (size_t)row * HID;
    const __nv_bfloat16* w = g_Wbf + (size_t)lab * HID;
    float s = 0.f;
    for (int i = tid; i < HID; i += 256)
        s += __bfloat162float(x[i]) * __bfloat162float(w[i]);
    __shared__ float red[256];
    red[tid] = s; __syncthreads();
    for (int o = 128; o; o >>= 1) {
        if (tid < o) red[tid] += red[tid + o];
        __syncthreads();
    }
    if (tid == 0) g_zlab[row] = red[0];
}

// ---------------------------------------------------------------------------
// 8) merge (max,sum) partials per row -> nll  (row range via row0)
// ---------------------------------------------------------------------------
__global__ __launch_bounds__(256) void k_reduce_lse(int row0) {
    int row = row0 + blockIdx.x, tid = threadIdx.x;
    __shared__ float red[256];
    float m = (tid < NTILE_N) ? g_pmax[(size_t)row * 256 + tid] : -3.0e38f;
    red[tid] = m; __syncthreads();
    for (int o = 128; o; o >>= 1) {
        if (tid < o) red[tid] = fmaxf(red[tid], red[tid + o]);
        __syncthreads();
    }
    float M = red[0]; __syncthreads();
    float s = (tid < NTILE_N) ? g_psum[(size_t)row * 256 + tid] * __expf(m - M) : 0.f;
    red[tid] = s; __syncthreads();
    for (int o = 128; o; o >>= 1) {
        if (tid < o) red[tid] += red[tid + o];
        __syncthreads();
    }
    if (tid == 0) g_nll[row] = M + logf(red[0]) - g_zlab[row];
}

// ---------------------------------------------------------------------------
// 9) masked means + final combination
// ---------------------------------------------------------------------------
__global__ __launch_bounds__(256) void k_final(float* __restrict__ out, int out_size,
                                               const int* __restrict__ starts,
                                               const int* __restrict__ ends,
                                               const int* __restrict__ am,
                                               const int* __restrict__ mam) {
    __shared__ double red[256];
    __shared__ int rl[2];
    __shared__ double totals[6];
    int tid = threadIdx.x;
    for (int i = tid; i < out_size; i += 256) out[i] = 0.f;
    __syncthreads();
    {
        int p0 = 0, p1 = 0;
        for (int s = tid; s < SEQ; s += 256) {
            p0 += am[s];
            p1 += am[SEQ + s];
        }
        red[tid] = (double)p0 + 65536.0 * (double)p1;
        __syncthreads();
        for (int o = 128; o; o >>= 1) {
            if (tid < o) red[tid] += red[tid + o];
            __syncthreads();
        }
        if (tid == 0) {
            long long packed = (long long)(red[0] + 0.5);
            rl[0] = (int)(packed & 0xFFFF);
            rl[1] = (int)(packed >> 16);
        }
        __syncthreads();
    }
    double sums[6] = {0, 0, 0, 0, 0, 0};
    for (int lin = tid; lin < 2 * (SEQ - 1); lin += 256) {
        int b = lin / (SEQ - 1), s = lin - b * (SEQ - 1);
        float v = g_nll[b * SEQ + s];
        int st = starts[b], en = ends[b];
        if (s >= st - 1 && s <= en - 1) { sums[0] += v; sums[1] += 1.0; }
        if (s >= en && s < rl[b] - 1)   { sums[2] += v; sums[3] += 1.0; }
    }
    for (int lin = tid; lin < BATCH * TMATH; lin += 256) {
        double w = (double)mam[lin];
        sums[4] += (double)g_nll[NMAIN + lin] * w;
        sums[5] += w;
    }
    for (int q = 0; q < 6; q++) {
        red[tid] = sums[q]; __syncthreads();
        for (int o = 128; o; o >>= 1) {
            if (tid < o) red[tid] += red[tid + o];
            __syncthreads();
        }
        if (tid == 0) totals[q] = red[0];
        __syncthreads();
    }
    if (tid == 0) {
        double stl = totals[0] / (totals[1] > 1.0 ? totals[1] : 1.0);
        double fal = totals[2] / (totals[3] > 1.0 ? totals[3] : 1.0);
        double ml  = totals[4] / (totals[5] > 1.0 ? totals[5] : 1.0);
        out[0] = (float)(0.5 * ml + 0.5 * stl + 0.4 * fal);
        if (out_size > 1) out[1] = (float)ml;
        if (out_size > 2) out[2] = (float)stl;
        if (out_size > 3) out[3] = (float)fal;
    }
}

// ---------------------------------------------------------------------------
// launch — R16 schedule + main-row reduce overlapped with math GEMM:
//   s0: convert_wx -> eW, GEMM main, [eZ] reduce(main), [eG] reduce(math), final
//   s1: inter, trans, [eW] zlab -> eZ, GEMM math -> eG
// ---------------------------------------------------------------------------
extern "C" void kernel_launch(void* const* d_in, const int* in_sizes, int n_in,
                              void* d_out, int out_size) {
    const float* hid       = (const float*)d_in[0];
    const int*   input_ids = (const int*)  d_in[1];
    const int*   am        = (const int*)  d_in[2];
    const int*   starts    = (const int*)  d_in[3];
    const int*   ends      = (const int*)  d_in[4];
    const int*   mlab      = (const int*)  d_in[5];
    const int*   mam       = (const int*)  d_in[6];
    const float* Am        = (const float*)d_in[8];
    const float* Bm        = (const float*)d_in[9];
    const float* bias      = (const float*)d_in[10];
    const float* W         = (const float*)d_in[11];
    float* out = (float*)d_out;

    cudaFuncSetAttribute(k_gemm_lse2, cudaFuncAttributeMaxDynamicSharedMemorySize,
                         SMEM_TOTAL);

    cudaStream_t s1;
    cudaStreamCreateWithFlags(&s1, cudaStreamNonBlocking);
    cudaEvent_t e0, eW, eZ, eG;
    cudaEventCreateWithFlags(&e0, cudaEventDisableTiming);
    cudaEventCreateWithFlags(&eW, cudaEventDisableTiming);
    cudaEventCreateWithFlags(&eZ, cudaEventDisableTiming);
    cudaEventCreateWithFlags(&eG, cudaEventDisableTiming);

    // fork side stream from the capture stream
    cudaEventRecord(e0, 0);
    cudaStreamWaitEvent(s1, e0, 0);

    // side stream: adapter chain (independent of W conversion)
    k_inter<<<dim3(128, 8), 128, 0, s1>>>(hid, Bm, starts);
    k_trans<<<dim3(128, 32), 256, 0, s1>>>(Am, bias);

    // main stream: single conversion launch, then main-row GEMM
    k_convert_wx<<<9216, 256>>>(W, hid);
    cudaEventRecord(eW, 0);
    k_gemm_lse2<<<dim3(32, NTILE_N), 256, SMEM_TOTAL>>>(0, starts);

    // side stream: zlab (-> eZ), then math-row GEMM (-> eG)
    cudaStreamWaitEvent(s1, eW, 0);
    k_zlab<<<NROWS, 256, 0, s1>>>(input_ids, mlab);
    cudaEventRecord(eZ, s1);
    k_gemm_lse2<<<dim3(16, NTILE_N), 256, SMEM_TOTAL, s1>>>(32, starts);
    cudaEventRecord(eG, s1);

    // main stream: main-row reduce overlaps the math GEMM, then the rest
    cudaStreamWaitEvent(0, eZ, 0);
    k_reduce_lse<<<NMAIN, 256>>>(0);
    cudaStreamWaitEvent(0, eG, 0);
    k_reduce_lse<<<NROWS - NMAIN, 256>>>(NMAIN);
    k_final<<<1, 256>>>(out, out_size, starts, ends, am, mam);
}